// round 13
// baseline (speedup 1.0000x reference)
#include <cuda_runtime.h>
#include <cuda_bf16.h>
#include <cstdint>

// Problem constants
#define NB      1024
#define SEQT    512
#define UNITS_  256
#define NCHARS  128
#define ZC      1024      // 4*UNITS

// Tiling: 128 blocks = 16 batch-tiles x 8 hidden-tiles
// blockIdx = bt*8 + ht ; each bt group of 8 consecutive blocks = one cluster
#define BM      64        // batch rows per block (GEMM M)
#define HN      32        // hidden units per block
#define BC      128       // z cols per block (GEMM N): col = gate*32 + unit
#define NBT     16
#define NHT     8
#define NBLK    128
#define NTHR    256

#define KDIM    256       // GEMM K
#define KPB     528       // padded row bytes (264 bf16)
#define ZP      132       // z row stride (floats)

// Shared memory layout (bytes)
#define OFF_WHI   0                         // Whi: [128 n][264 k] bf16 = 67584
#define OFF_WLO   67584                     // Wlo: 67584
#define OFF_AHI   135168                    // Ahi: [64 r][264 k] bf16 = 33792
#define OFF_ALO   168960                    // Alo: 33792
#define OFF_Z     OFF_AHI                   // z: [64][132] fp32 = 33792 (overlay)
#define SMEM_TOTAL 202752

// Device-global scratch (zero-init at load). Producer-split bf16 h state.
__device__ __nv_bfloat16 g_hhi[2][NB * UNITS_];
__device__ __nv_bfloat16 g_hlo[2][NB * UNITS_];

__device__ __forceinline__ uint32_t smem_u32(const void* p) {
    uint32_t a;
    asm("{ .reg .u64 t; cvta.to.shared.u64 t, %1; cvt.u32.u64 %0, t; }" : "=r"(a) : "l"(p));
    return a;
}

__device__ __forceinline__ float fast_sigmoid(float x) {
    return __fdividef(1.0f, 1.0f + __expf(-x));
}
__device__ __forceinline__ float fast_tanh(float x) {
    float e = __expf(2.0f * x);
    return 1.0f - __fdividef(2.0f, e + 1.0f);
}

// m16n8k16 row.col bf16 -> fp32 accumulate (baseline PTX)
__device__ __forceinline__ void mma16816(float& c0, float& c1, float& c2, float& c3,
                                         uint32_t a0, uint32_t a1, uint32_t a2, uint32_t a3,
                                         uint32_t b0, uint32_t b1) {
    asm volatile(
        "mma.sync.aligned.m16n8k16.row.col.f32.bf16.bf16.f32 "
        "{%0,%1,%2,%3}, {%4,%5,%6,%7}, {%8,%9}, {%0,%1,%2,%3};"
        : "+f"(c0), "+f"(c1), "+f"(c2), "+f"(c3)
        : "r"(a0), "r"(a1), "r"(a2), "r"(a3), "r"(b0), "r"(b1));
}

// ldmatrix x4 (baseline PTX sm_75+)
#define LDSM4(r, addr) \
    asm volatile("ldmatrix.sync.aligned.m8n8.x4.shared.b16 {%0,%1,%2,%3}, [%4];" \
        : "=r"((r)[0]), "=r"((r)[1]), "=r"((r)[2]), "=r"((r)[3]) : "r"(addr))

// cp.async 16B, L2-only (cg). src is a global generic pointer.
#define CP_ASYNC16(dst, src) \
    asm volatile("cp.async.cg.shared.global [%0], [%1], 16;" \
        :: "r"(dst), "l"(__cvta_generic_to_global((const void*)(src))) : "memory")
#define CP_COMMIT()  asm volatile("cp.async.commit_group;" ::: "memory")
#define CP_WAIT(n)   asm volatile("cp.async.wait_group %0;" :: "n"(n) : "memory")

// Cluster barrier (baseline sm_90 PTX)
#define CLUSTER_ARRIVE() asm volatile("barrier.cluster.arrive.aligned;" ::: "memory")
#define CLUSTER_WAIT()   asm volatile("barrier.cluster.wait.aligned;" ::: "memory")

// One K-half (8 k-chunks) of the 3-pass MMA. kbase = 0 or 256 bytes.
__device__ __forceinline__ void mma_half(float acc[2][4][4],
                                         uint32_t ahi0, uint32_t alo0,
                                         uint32_t bhi0, uint32_t blo0, int kbase)
{
#pragma unroll 2
    for (int kc = 0; kc < 8; kc++) {
        const int kb = kbase + kc * 32;   // 16 bf16 = 32 bytes
        uint32_t ah0[4], ah1[4], al0[4], al1[4];
        uint32_t bh0[4], bh1[4], bl0[4], bl1[4];
        LDSM4(ah0, ahi0 + kb);
        LDSM4(ah1, ahi0 + 16 * KPB + kb);
        LDSM4(al0, alo0 + kb);
        LDSM4(al1, alo0 + 16 * KPB + kb);
        LDSM4(bh0, bhi0 + kb);
        LDSM4(bh1, bhi0 + 16 * KPB + kb);
        LDSM4(bl0, blo0 + kb);
        LDSM4(bl1, blo0 + 16 * KPB + kb);
        uint32_t* ahp[2] = {ah0, ah1};
        uint32_t* alp[2] = {al0, al1};
        uint32_t* bhj[4] = {bh0, bh0 + 2, bh1, bh1 + 2};
        uint32_t* blj[4] = {bl0, bl0 + 2, bl1, bl1 + 2};
#pragma unroll
        for (int j = 0; j < 4; j++) {
#pragma unroll
            for (int ms = 0; ms < 2; ms++) {
                mma16816(acc[ms][j][0], acc[ms][j][1], acc[ms][j][2], acc[ms][j][3],
                         ahp[ms][0], ahp[ms][1], ahp[ms][2], ahp[ms][3],
                         bhj[j][0], bhj[j][1]);
                mma16816(acc[ms][j][0], acc[ms][j][1], acc[ms][j][2], acc[ms][j][3],
                         alp[ms][0], alp[ms][1], alp[ms][2], alp[ms][3],
                         bhj[j][0], bhj[j][1]);
                mma16816(acc[ms][j][0], acc[ms][j][1], acc[ms][j][2], acc[ms][j][3],
                         ahp[ms][0], ahp[ms][1], ahp[ms][2], ahp[ms][3],
                         blj[j][0], blj[j][1]);
            }
        }
    }
}

extern "C" __global__ void __launch_bounds__(NTHR, 1) __cluster_dims__(NHT, 1, 1)
lstm_hmma_kernel(const int*   __restrict__ inputs,   // [NB, SEQT]
                 const float* __restrict__ Wx,       // [NCHARS, ZC]
                 const float* __restrict__ Wh,       // [UNITS, ZC]
                 const float* __restrict__ bias,     // [ZC]
                 const float* __restrict__ Wd,       // [UNITS, NCHARS]
                 const float* __restrict__ bd,       // [NCHARS]
                 float*       __restrict__ out)      // [NB, NCHARS]
{
    extern __shared__ char smem[];
    float* z_s = (float*)(smem + OFF_Z);
    const uint32_t sb = smem_u32(smem);

    const int tid  = threadIdx.x;
    const int wid  = tid >> 5;
    const int lane = tid & 31;
    const int bt   = blockIdx.x >> 3;   // 0..15 (cluster group)
    const int ht   = blockIdx.x & 7;    // 0..7  (cluster rank)
    const int b0   = bt * BM;

    // ---- One-time: Wh slice -> bf16 hi/lo, [n][k] with n = gate*32 + unit ----
    for (int idx = tid; idx < BC * KDIM; idx += NTHR) {
        int n = idx >> 8;          // 0..127
        int k = idx & 255;         // 0..255
        int gcol = ((n >> 5) << 8) + ht * HN + (n & 31);
        float w = Wh[k * ZC + gcol];
        __nv_bfloat16 hi = __float2bfloat16(w);
        __nv_bfloat16 lo = __float2bfloat16(w - __bfloat162float(hi));
        *(__nv_bfloat16*)(smem + OFF_WHI + n * KPB + k * 2) = hi;
        *(__nv_bfloat16*)(smem + OFF_WLO + n * KPB + k * 2) = lo;
    }

    // Bias -> registers (coalesced: u = lane)
    const int u = lane;
    float breg[4];
#pragma unroll
    for (int gt = 0; gt < 4; gt++)
        breg[gt] = __ldg(&bias[gt * 256 + ht * HN + u]);

    // zero z region (t=0 gate phase reads zeros)
    for (int idx = tid; idx < BM * ZP; idx += NTHR) z_s[idx] = 0.0f;

    float creg[8];
#pragma unroll
    for (int j = 0; j < 8; j++) creg[j] = 0.0f;

    // MMA warp mapping: warp tile m32 x n32; Wm=2 (wm=wid&1), Wn=4 (wn=wid>>1)
    const int g  = lane >> 2;      // 0..7
    const int tg = lane & 3;       // 0..3
    const int wm = wid & 1;
    const int wn = wid >> 1;

    // ldmatrix per-lane row addresses (x4 matrix order matches mma frag order)
    const int l7 = lane & 7;
    const int qq = lane >> 3;      // quad 0..3
    const uint32_t ahi0 = sb + OFF_AHI + (uint32_t)((32 * wm + l7 + 8 * (qq & 1)) * KPB + 16 * (qq >> 1));
    const uint32_t alo0 = sb + OFF_ALO + (uint32_t)((32 * wm + l7 + 8 * (qq & 1)) * KPB + 16 * (qq >> 1));
    const uint32_t bhi0 = sb + OFF_WHI + (uint32_t)((32 * wn + 8 * (qq >> 1) + l7) * KPB + 16 * (qq & 1));
    const uint32_t blo0 = sb + OFF_WLO + (uint32_t)((32 * wn + 8 * (qq >> 1) + l7) * KPB + 16 * (qq & 1));

    __syncthreads();

    for (int t = 0; t < SEQT; t++) {
        const int cur = t & 1;
        const int nxt = cur ^ 1;

        if (t > 0) {
            // ---- Stage A via cp.async: two commit groups (K halves) ----
            const __nv_bfloat16* hhi = g_hhi[cur];
            const __nv_bfloat16* hlo = g_hlo[cur];
#pragma unroll
            for (int half = 0; half < 2; half++) {
                const int ke = half * 128;          // k elem base
                const int kby = half * 256;         // smem byte base
#pragma unroll
                for (int i = 0; i < 4; i++) {
                    int idx = tid + i * NTHR;       // 0..1023
                    int r = idx >> 4;               // 0..63
                    int c = idx & 15;               // 0..15 (16B chunks)
                    const __nv_bfloat16* sh = hhi + (b0 + r) * UNITS_ + ke + c * 8;
                    const __nv_bfloat16* sl = hlo + (b0 + r) * UNITS_ + ke + c * 8;
                    uint32_t dh = sb + OFF_AHI + (uint32_t)(r * KPB + kby + c * 16);
                    uint32_t dl = sb + OFF_ALO + (uint32_t)(r * KPB + kby + c * 16);
                    CP_ASYNC16(dh, sh);
                    CP_ASYNC16(dl, sl);
                }
                CP_COMMIT();
            }
        }

        // ---- Chars + Wx gather (normal LDGs; overlap the cp.async drain) ----
        int ch[8];
#pragma unroll
        for (int j = 0; j < 8; j++)
            ch[j] = __ldg(&inputs[(b0 + wid + 8 * j) * SEQT + t]);
        float xv0[8], xv1[8], xv2[8], xv3[8];
#pragma unroll
        for (int j = 0; j < 8; j++) {
            const float* wxr = Wx + ch[j] * ZC + ht * HN + u;
            xv0[j] = __ldg(wxr);
            xv1[j] = __ldg(wxr + 256);
            xv2[j] = __ldg(wxr + 512);
            xv3[j] = __ldg(wxr + 768);
        }

        if (t > 0) {
            float acc[2][4][4];
#pragma unroll
            for (int ms = 0; ms < 2; ms++)
#pragma unroll
                for (int j = 0; j < 4; j++) {
                    acc[ms][j][0] = 0.f; acc[ms][j][1] = 0.f;
                    acc[ms][j][2] = 0.f; acc[ms][j][3] = 0.f;
                }

            CP_WAIT(1);        // lower half landed
            __syncthreads();
            mma_half(acc, ahi0, alo0, bhi0, blo0, 0);

            CP_WAIT(0);        // upper half landed
            __syncthreads();
            mma_half(acc, ahi0, alo0, bhi0, blo0, 256);

            __syncthreads();   // all A reads done before z overlays A_hi

            // ---- Store z tile (m32n32 accumulator layout -> [row][col]) ----
#pragma unroll
            for (int ms = 0; ms < 2; ms++)
#pragma unroll
                for (int j = 0; j < 4; j++) {
                    int row0 = 32 * wm + 16 * ms + g;
                    int col  = 32 * wn + 8 * j + 2 * tg;
                    *(float2*)(z_s + row0 * ZP + col)       = make_float2(acc[ms][j][0], acc[ms][j][1]);
                    *(float2*)(z_s + (row0 + 8) * ZP + col) = make_float2(acc[ms][j][2], acc[ms][j][3]);
                }
            __syncthreads();
        }

        // ---- Gate phase: coalesced mapping (b = wid + 8j, unit u = lane) ----
#pragma unroll
        for (int j = 0; j < 8; j++) {
            int b = wid + 8 * j;
            float zi = z_s[b * ZP +      u] + xv0[j] + breg[0];
            float zf = z_s[b * ZP + 32 + u] + xv1[j] + breg[1];
            float zg = z_s[b * ZP + 64 + u] + xv2[j] + breg[2];
            float zo = z_s[b * ZP + 96 + u] + xv3[j] + breg[3];
            float ig = fast_sigmoid(zi);
            float fg = fast_sigmoid(zf);
            float og = fast_sigmoid(zo);
            float gg = fast_tanh(zg);
            float c  = fmaf(fg, creg[j], ig * gg);
            creg[j] = c;
            float h  = og * fast_tanh(c);
            __nv_bfloat16 hh = __float2bfloat16(h);
            __nv_bfloat16 hl = __float2bfloat16(h - __bfloat162float(hh));
            int gaddr = (b0 + b) * UNITS_ + ht * HN + u;
            g_hhi[nxt][gaddr] = hh;
            g_hlo[nxt][gaddr] = hl;
        }

        // ---- Cluster barrier: h(t+1) visible to the 7 peer blocks ----
        __threadfence();
        CLUSTER_ARRIVE();
        CLUSTER_WAIT();
    }

    // ---- Final stage: logits = h_final @ Wd + bd ; softmax ----
    // Final h in buffer 0 (t=511: nxt=0). Each block: 8 batch rows (own bt tile).
    const int rowbase = blockIdx.x * 8;
    float* wd_s   = (float*)smem;               // 128KB (WHI+WLO region)
    float* hrow_s = (float*)(smem + OFF_ALO);   // 8x256 fp32
    float* lg     = (float*)(smem + OFF_ALO + 8 * 256 * 4); // 8x128 logits

    for (int idx = tid; idx < UNITS_ * NCHARS; idx += NTHR)
        wd_s[idx] = Wd[idx];
    for (int idx = tid; idx < 8 * UNITS_; idx += NTHR) {
        int r  = idx >> 8;
        int uu = idx & 255;
        int ga = (rowbase + r) * UNITS_ + uu;
        hrow_s[idx] = __bfloat162float(g_hhi[0][ga]) + __bfloat162float(g_hlo[0][ga]);
    }
    __syncthreads();

    {
        int n  = tid & 127;
        int rr = tid >> 7;
#pragma unroll
        for (int q = 0; q < 4; q++) {
            int row = q * 2 + rr;
            float a = bd[n];
#pragma unroll 8
            for (int uu = 0; uu < UNITS_; uu++)
                a = fmaf(hrow_s[row * UNITS_ + uu], wd_s[uu * NCHARS + n], a);
            lg[row * NCHARS + n] = a;
        }
    }
    __syncthreads();

    {   // softmax: one warp per row
        int w = tid >> 5;
        float v[4];
        float mx = -3.402823466e38f;
#pragma unroll
        for (int q = 0; q < 4; q++) {
            v[q] = lg[w * NCHARS + lane + 32 * q];
            mx = fmaxf(mx, v[q]);
        }
#pragma unroll
        for (int s = 16; s > 0; s >>= 1) mx = fmaxf(mx, __shfl_xor_sync(0xFFFFFFFFu, mx, s));
        float sum = 0.f;
#pragma unroll
        for (int q = 0; q < 4; q++) { v[q] = __expf(v[q] - mx); sum += v[q]; }
#pragma unroll
        for (int s = 16; s > 0; s >>= 1) sum += __shfl_xor_sync(0xFFFFFFFFu, sum, s);
        float inv = 1.0f / sum;
        int bg = rowbase + w;
#pragma unroll
        for (int q = 0; q < 4; q++)
            out[bg * NCHARS + lane + 32 * q] = v[q] * inv;
    }
}

extern "C" void kernel_launch(void* const* d_in, const int* in_sizes, int n_in,
                              void* d_out, int out_size) {
    const int*   inputs = (const int*)  d_in[0];
    const float* Wx     = (const float*)d_in[1];
    const float* Wh     = (const float*)d_in[2];
    const float* b      = (const float*)d_in[3];
    const float* Wd     = (const float*)d_in[4];
    const float* bd     = (const float*)d_in[5];
    float* out = (float*)d_out;

    cudaFuncSetAttribute(lstm_hmma_kernel,
                         cudaFuncAttributeMaxDynamicSharedMemorySize, SMEM_TOTAL);

    lstm_hmma_kernel<<<NBLK, NTHR, SMEM_TOTAL>>>(inputs, Wx, Wh, b, Wd, bd, out);
}

// round 16
// speedup vs baseline: 1.6906x; 1.6906x over previous
#include <cuda_runtime.h>
#include <cuda_bf16.h>
#include <cstdint>

// Problem constants
#define NB      1024
#define SEQT    512
#define UNITS_  256
#define NCHARS  128
#define ZC      1024      // 4*UNITS

// Tiling: 128 blocks = 16 batch-tiles x 8 hidden-tiles
// blockIdx = bt*8 + ht  (contiguous 8-block groups share a batch tile)
#define BM      64        // batch rows per block (GEMM M)
#define HN      32        // hidden units per block
#define BC      128       // z cols per block (GEMM N): col = 4*unit + gate
#define NBT     16
#define NHT     8
#define NBLK    128
#define NTHR    256
#define GRPSZ   8         // blocks per barrier group (same bt)

#define KDIM    256       // GEMM K
#define KPB     528       // padded row bytes (264 bf16)
#define ZP      132       // z row stride (floats)

// Shared memory layout (bytes)
#define OFF_WHI   0                         // Whi: [128 n][264 k] bf16 = 67584
#define OFF_WLO   67584                     // Wlo: 67584
#define OFF_AHI   135168                    // Ahi: [64 r][264 k] bf16 = 33792
#define OFF_ALO   168960                    // Alo: 33792
#define OFF_Z     OFF_AHI                   // z: [64][132] fp32 = 33792 (overlay)
#define SMEM_TOTAL 202752

// Device-global scratch (zero-init at load)
__device__ unsigned int g_hx[2][NB * UNITS_];   // packed (bf16 hi | bf16 lo<<16)
struct GSync { unsigned int count; unsigned int gen; unsigned int pad[30]; };
__device__ GSync g_sync[NBT];                   // one 128B line per group

__device__ __forceinline__ uint32_t smem_u32(const void* p) {
    uint32_t a;
    asm("{ .reg .u64 t; cvta.to.shared.u64 t, %1; cvt.u32.u64 %0, t; }" : "=r"(a) : "l"(p));
    return a;
}

// Hardware tanh (1 MUFU). Saturates cleanly; max rel err ~2^-11.
__device__ __forceinline__ float tanh_ap(float x) {
    float y;
    asm("tanh.approx.f32 %0, %1;" : "=f"(y) : "f"(x));
    return y;
}
__device__ __forceinline__ float sigmoid_ap(float x) {
    return fmaf(0.5f, tanh_ap(0.5f * x), 0.5f);
}

// m16n8k16 row.col bf16 -> fp32 accumulate (baseline PTX)
__device__ __forceinline__ void mma16816(float& c0, float& c1, float& c2, float& c3,
                                         uint32_t a0, uint32_t a1, uint32_t a2, uint32_t a3,
                                         uint32_t b0, uint32_t b1) {
    asm volatile(
        "mma.sync.aligned.m16n8k16.row.col.f32.bf16.bf16.f32 "
        "{%0,%1,%2,%3}, {%4,%5,%6,%7}, {%8,%9}, {%0,%1,%2,%3};"
        : "+f"(c0), "+f"(c1), "+f"(c2), "+f"(c3)
        : "r"(a0), "r"(a1), "r"(a2), "r"(a3), "r"(b0), "r"(b1));
}

// ldmatrix x4 (baseline PTX sm_75+)
#define LDSM4(r, addr) \
    asm volatile("ldmatrix.sync.aligned.m8n8.x4.shared.b16 {%0,%1,%2,%3}, [%4];" \
        : "=r"((r)[0]), "=r"((r)[1]), "=r"((r)[2]), "=r"((r)[3]) : "r"(addr))

// Sense-reversing barrier over the GRPSZ co-resident CTAs sharing one batch tile.
__device__ __forceinline__ void group_barrier(int grp) {
    __syncthreads();
    if (threadIdx.x == 0) {
        __threadfence();
        unsigned int gen = *(volatile unsigned int*)&g_sync[grp].gen;
        unsigned int c = atomicAdd(&g_sync[grp].count, 1u);
        if (c == GRPSZ - 1u) {
            atomicExch(&g_sync[grp].count, 0u);
            __threadfence();
            atomicAdd(&g_sync[grp].gen, 1u);
        } else {
            while (*(volatile unsigned int*)&g_sync[grp].gen == gen) { __nanosleep(16); }
        }
        __threadfence();
    }
    __syncthreads();
}

// One K-half (8 k-chunks) of the 3-pass MMA. kbase = 0 or 256 bytes.
__device__ __forceinline__ void mma_half(float acc[2][4][4],
                                         uint32_t ahi0, uint32_t alo0,
                                         uint32_t bhi0, uint32_t blo0, int kbase)
{
#pragma unroll 2
    for (int kc = 0; kc < 8; kc++) {
        const int kb = kbase + kc * 32;   // 16 bf16 = 32 bytes
        uint32_t ah0[4], ah1[4], al0[4], al1[4];
        uint32_t bh0[4], bh1[4], bl0[4], bl1[4];
        LDSM4(ah0, ahi0 + kb);
        LDSM4(ah1, ahi0 + 16 * KPB + kb);
        LDSM4(al0, alo0 + kb);
        LDSM4(al1, alo0 + 16 * KPB + kb);
        LDSM4(bh0, bhi0 + kb);
        LDSM4(bh1, bhi0 + 16 * KPB + kb);
        LDSM4(bl0, blo0 + kb);
        LDSM4(bl1, blo0 + 16 * KPB + kb);
        uint32_t* ahp[2] = {ah0, ah1};
        uint32_t* alp[2] = {al0, al1};
        uint32_t* bhj[4] = {bh0, bh0 + 2, bh1, bh1 + 2};
        uint32_t* blj[4] = {bl0, bl0 + 2, bl1, bl1 + 2};
#pragma unroll
        for (int j = 0; j < 4; j++) {
#pragma unroll
            for (int ms = 0; ms < 2; ms++) {
                mma16816(acc[ms][j][0], acc[ms][j][1], acc[ms][j][2], acc[ms][j][3],
                         ahp[ms][0], ahp[ms][1], ahp[ms][2], ahp[ms][3],
                         bhj[j][0], bhj[j][1]);
                mma16816(acc[ms][j][0], acc[ms][j][1], acc[ms][j][2], acc[ms][j][3],
                         alp[ms][0], alp[ms][1], alp[ms][2], alp[ms][3],
                         bhj[j][0], bhj[j][1]);
                mma16816(acc[ms][j][0], acc[ms][j][1], acc[ms][j][2], acc[ms][j][3],
                         ahp[ms][0], ahp[ms][1], ahp[ms][2], ahp[ms][3],
                         blj[j][0], blj[j][1]);
            }
        }
    }
}

extern "C" __global__ void __launch_bounds__(NTHR, 1)
lstm_hmma_kernel(const int*   __restrict__ inputs,   // [NB, SEQT]
                 const float* __restrict__ Wx,       // [NCHARS, ZC]
                 const float* __restrict__ Wh,       // [UNITS, ZC]
                 const float* __restrict__ bias,     // [ZC]
                 const float* __restrict__ Wd,       // [UNITS, NCHARS]
                 const float* __restrict__ bd,       // [NCHARS]
                 float*       __restrict__ out)      // [NB, NCHARS]
{
    extern __shared__ char smem[];
    float* z_s = (float*)(smem + OFF_Z);
    const uint32_t sb = smem_u32(smem);

    const int tid  = threadIdx.x;
    const int wid  = tid >> 5;
    const int lane = tid & 31;
    const int bt   = blockIdx.x >> 3;   // 0..15 (barrier group)
    const int ht   = blockIdx.x & 7;    // 0..7
    const int b0   = bt * BM;

    // ---- One-time: Wh slice -> bf16 hi/lo, INTERLEAVED cols: n = 4*unit + gate ----
    // local col n -> global col: gate(n&3)*256 + ht*32 + unit(n>>2)
    for (int idx = tid; idx < BC * KDIM; idx += NTHR) {
        int n = idx >> 8;          // 0..127
        int k = idx & 255;         // 0..255
        int gcol = ((n & 3) << 8) + ht * HN + (n >> 2);
        float w = Wh[k * ZC + gcol];
        __nv_bfloat16 hi = __float2bfloat16(w);
        __nv_bfloat16 lo = __float2bfloat16(w - __bfloat162float(hi));
        *(__nv_bfloat16*)(smem + OFF_WHI + n * KPB + k * 2) = hi;
        *(__nv_bfloat16*)(smem + OFF_WLO + n * KPB + k * 2) = lo;
    }

    // Bias -> registers (coalesced: u = lane)
    const int u = lane;
    float breg[4];
#pragma unroll
    for (int gt = 0; gt < 4; gt++)
        breg[gt] = __ldg(&bias[gt * 256 + ht * HN + u]);

    // zero z region (t=0 gate phase reads zeros)
    for (int idx = tid; idx < BM * ZP; idx += NTHR) z_s[idx] = 0.0f;

    float creg[8];
#pragma unroll
    for (int j = 0; j < 8; j++) creg[j] = 0.0f;

    // MMA warp mapping: warp tile m32 x n32; Wm=2 (wm=wid&1), Wn=4 (wn=wid>>1)
    const int g  = lane >> 2;      // 0..7
    const int tg = lane & 3;       // 0..3
    const int wm = wid & 1;
    const int wn = wid >> 1;

    // ldmatrix per-lane row addresses (x4 matrix order matches mma frag order)
    const int l7 = lane & 7;
    const int qq = lane >> 3;      // quad 0..3
    const uint32_t ahi0 = sb + OFF_AHI + (uint32_t)((32 * wm + l7 + 8 * (qq & 1)) * KPB + 16 * (qq >> 1));
    const uint32_t alo0 = sb + OFF_ALO + (uint32_t)((32 * wm + l7 + 8 * (qq & 1)) * KPB + 16 * (qq >> 1));
    const uint32_t bhi0 = sb + OFF_WHI + (uint32_t)((32 * wn + 8 * (qq >> 1) + l7) * KPB + 16 * (qq & 1));
    const uint32_t blo0 = sb + OFF_WLO + (uint32_t)((32 * wn + 8 * (qq >> 1) + l7) * KPB + 16 * (qq & 1));

    __syncthreads();

    for (int t = 0; t < SEQT; t++) {
        const int cur = t & 1;
        const int nxt = cur ^ 1;

        // ---- Chars (warp-broadcast) ----
        int ch[8];
#pragma unroll
        for (int j = 0; j < 8; j++)
            ch[j] = __ldg(&inputs[(b0 + wid + 8 * j) * SEQT + t]);

        uint4 pp[8];   // upper-half h words, in flight across lower-half MMA
        if (t > 0) {
            // ---- Stage A lower K half: k in [0,128) ----
#pragma unroll
            for (int i = 0; i < 8; i++) {
                int gidx = tid + i * NTHR;      // over BM*32 groups
                int r  = gidx >> 5;
                int kq = gidx & 31;             // k0 = 4*kq
                uint4 p = *(const uint4*)&g_hx[cur][(b0 + r) * UNITS_ + 4 * kq];
                uint32_t hi01 = __byte_perm(p.x, p.y, 0x5410);
                uint32_t hi23 = __byte_perm(p.z, p.w, 0x5410);
                uint32_t lo01 = __byte_perm(p.x, p.y, 0x7632);
                uint32_t lo23 = __byte_perm(p.z, p.w, 0x7632);
                uint32_t byte = (uint32_t)(r * KPB + 8 * kq);
                *(uint2*)(smem + OFF_AHI + byte) = make_uint2(hi01, hi23);
                *(uint2*)(smem + OFF_ALO + byte) = make_uint2(lo01, lo23);
            }
            // ---- Issue upper-half LDGs (latency hidden under lower-half MMA) ----
#pragma unroll
            for (int i = 0; i < 8; i++) {
                int gidx = tid + i * NTHR;
                int r  = gidx >> 5;
                int kq = 32 + (gidx & 31);
                pp[i] = *(const uint4*)&g_hx[cur][(b0 + r) * UNITS_ + 4 * kq];
            }
        }

        // ---- Wx gather (coalesced; overlaps staging/MMA latency) ----
        float xv0[8], xv1[8], xv2[8], xv3[8];
#pragma unroll
        for (int j = 0; j < 8; j++) {
            const float* wxr = Wx + ch[j] * ZC + ht * HN + u;
            xv0[j] = __ldg(wxr);
            xv1[j] = __ldg(wxr + 256);
            xv2[j] = __ldg(wxr + 512);
            xv3[j] = __ldg(wxr + 768);
        }

        if (t > 0) {
            float acc[2][4][4];
#pragma unroll
            for (int ms = 0; ms < 2; ms++)
#pragma unroll
                for (int j = 0; j < 4; j++) {
                    acc[ms][j][0] = 0.f; acc[ms][j][1] = 0.f;
                    acc[ms][j][2] = 0.f; acc[ms][j][3] = 0.f;
                }

            __syncthreads();   // lower-half staging visible

            // ---- MMA on lower K half (upper-half LDGs still in flight) ----
            mma_half(acc, ahi0, alo0, bhi0, blo0, 0);

            // ---- Store upper half (disjoint bytes from lower-half reads) ----
#pragma unroll
            for (int i = 0; i < 8; i++) {
                int gidx = tid + i * NTHR;
                int r  = gidx >> 5;
                int kq = 32 + (gidx & 31);
                uint4 p = pp[i];
                uint32_t hi01 = __byte_perm(p.x, p.y, 0x5410);
                uint32_t hi23 = __byte_perm(p.z, p.w, 0x5410);
                uint32_t lo01 = __byte_perm(p.x, p.y, 0x7632);
                uint32_t lo23 = __byte_perm(p.z, p.w, 0x7632);
                uint32_t byte = (uint32_t)(r * KPB + 8 * kq);
                *(uint2*)(smem + OFF_AHI + byte) = make_uint2(hi01, hi23);
                *(uint2*)(smem + OFF_ALO + byte) = make_uint2(lo01, lo23);
            }
            __syncthreads();   // upper-half staging visible

            // ---- MMA on upper K half ----
            mma_half(acc, ahi0, alo0, bhi0, blo0, 256);

            __syncthreads();   // all A reads done before z overlays A_hi

            // ---- Store z tile (m32n32 accumulator layout -> [row][col]) ----
#pragma unroll
            for (int ms = 0; ms < 2; ms++)
#pragma unroll
                for (int j = 0; j < 4; j++) {
                    int row0 = 32 * wm + 16 * ms + g;
                    int col  = 32 * wn + 8 * j + 2 * tg;
                    *(float2*)(z_s + row0 * ZP + col)       = make_float2(acc[ms][j][0], acc[ms][j][1]);
                    *(float2*)(z_s + (row0 + 8) * ZP + col) = make_float2(acc[ms][j][2], acc[ms][j][3]);
                }
            __syncthreads();
        }

        // ---- Gate phase: coalesced (b = wid + 8j); z cols interleaved 4u+gate ----
#pragma unroll
        for (int j = 0; j < 8; j++) {
            int b = wid + 8 * j;
            float4 q = *(const float4*)(z_s + b * ZP + 4 * u);
            float zi = q.x + xv0[j] + breg[0];
            float zf = q.y + xv1[j] + breg[1];
            float zg = q.z + xv2[j] + breg[2];
            float zo = q.w + xv3[j] + breg[3];
            float ig = sigmoid_ap(zi);
            float fg = sigmoid_ap(zf);
            float og = sigmoid_ap(zo);
            float gg = tanh_ap(zg);
            float c  = fmaf(fg, creg[j], ig * gg);
            creg[j] = c;
            float h  = og * tanh_ap(c);
            __nv_bfloat16 hh = __float2bfloat16(h);
            __nv_bfloat16 hl = __float2bfloat16(h - __bfloat162float(hh));
            unsigned int word = (unsigned int)__bfloat16_as_ushort(hh) |
                                ((unsigned int)__bfloat16_as_ushort(hl) << 16);
            g_hx[nxt][(b0 + b) * UNITS_ + ht * HN + u] = word;
        }

        group_barrier(bt);   // only the 8 blocks sharing this batch tile
    }

    // ---- Final stage: logits = h_final @ Wd + bd ; softmax ----
    const int rowbase = blockIdx.x * 8;
    float* wd_s   = (float*)smem;               // 128KB (WHI+WLO region)
    float* hrow_s = (float*)(smem + OFF_ALO);   // 8x256 fp32
    float* lg     = (float*)(smem + OFF_ALO + 8 * 256 * 4); // 8x128 logits

    for (int idx = tid; idx < UNITS_ * NCHARS; idx += NTHR)
        wd_s[idx] = Wd[idx];
    for (int idx = tid; idx < 8 * UNITS_; idx += NTHR) {
        int r  = idx >> 8;
        int uu = idx & 255;
        unsigned int word = g_hx[0][(rowbase + r) * UNITS_ + uu];
        float h = __bfloat162float(__ushort_as_bfloat16((unsigned short)(word & 0xFFFF))) +
                  __bfloat162float(__ushort_as_bfloat16((unsigned short)(word >> 16)));
        hrow_s[idx] = h;
    }
    __syncthreads();

    {
        int n  = tid & 127;
        int rr = tid >> 7;
#pragma unroll
        for (int q = 0; q < 4; q++) {
            int row = q * 2 + rr;
            float a = bd[n];
#pragma unroll 8
            for (int uu = 0; uu < UNITS_; uu++)
                a = fmaf(hrow_s[row * UNITS_ + uu], wd_s[uu * NCHARS + n], a);
            lg[row * NCHARS + n] = a;
        }
    }
    __syncthreads();

    {   // softmax: one warp per row (accurate __expf path)
        int w = tid >> 5;
        float v[4];
        float mx = -3.402823466e38f;
#pragma unroll
        for (int q = 0; q < 4; q++) {
            v[q] = lg[w * NCHARS + lane + 32 * q];
            mx = fmaxf(mx, v[q]);
        }
#pragma unroll
        for (int s = 16; s > 0; s >>= 1) mx = fmaxf(mx, __shfl_xor_sync(0xFFFFFFFFu, mx, s));
        float sum = 0.f;
#pragma unroll
        for (int q = 0; q < 4; q++) { v[q] = __expf(v[q] - mx); sum += v[q]; }
#pragma unroll
        for (int s = 16; s > 0; s >>= 1) sum += __shfl_xor_sync(0xFFFFFFFFu, sum, s);
        float inv = 1.0f / sum;
        int bg = rowbase + w;
#pragma unroll
        for (int q = 0; q < 4; q++)
            out[bg * NCHARS + lane + 32 * q] = v[q] * inv;
    }
}

extern "C" void kernel_launch(void* const* d_in, const int* in_sizes, int n_in,
                              void* d_out, int out_size) {
    const int*   inputs = (const int*)  d_in[0];
    const float* Wx     = (const float*)d_in[1];
    const float* Wh     = (const float*)d_in[2];
    const float* b      = (const float*)d_in[3];
    const float* Wd     = (const float*)d_in[4];
    const float* bd     = (const float*)d_in[5];
    float* out = (float*)d_out;

    cudaFuncSetAttribute(lstm_hmma_kernel,
                         cudaFuncAttributeMaxDynamicSharedMemorySize, SMEM_TOTAL);

    lstm_hmma_kernel<<<NBLK, NTHR, SMEM_TOTAL>>>(inputs, Wx, Wh, b, Wd, bd, out);
}

// round 17
// speedup vs baseline: 1.9580x; 1.1582x over previous
#include <cuda_runtime.h>
#include <cuda_bf16.h>
#include <cstdint>

// Problem constants
#define NB      1024
#define SEQT    512
#define UNITS_  256
#define NCHARS  128
#define ZC      1024      // 4*UNITS

// Tiling: 128 blocks = 16 batch-tiles x 8 hidden-tiles
// blockIdx = bt*8 + ht  (contiguous 8-block groups share a batch tile)
#define BM      64        // batch rows per block (GEMM M)
#define HN      32        // hidden units per block
#define BC      128       // z cols per block (GEMM N): col = 4*unit + gate
#define NBT     16
#define NHT     8
#define NBLK    128
#define NTHR    256
#define GRPSZ   8         // blocks per barrier group (same bt)

#define KDIM    256       // GEMM K
#define KPB     528       // padded row bytes (264 bf16)
#define ZP      132       // z row stride (floats)

// Shared memory layout (bytes)
#define OFF_WHI   0                         // Whi: [128 n][264 k] bf16 = 67584
#define OFF_WLO   67584                     // Wlo: 67584
#define OFF_AHI   135168                    // Ahi: [64 r][264 k] bf16 = 33792
#define OFF_ALO   168960                    // Alo: 33792
#define OFF_Z     OFF_AHI                   // z: [64][132] fp32 = 33792 (overlay)
#define SMEM_TOTAL 202752

// Device-global scratch (zero-init at load)
__device__ unsigned int g_hx[2][NB * UNITS_];   // packed (bf16 hi | bf16 lo<<16)
// Monotonic per-block arrival flags (one 128B line each; never reset -> replay-safe)
struct GFlag { unsigned int v; unsigned int pad[31]; };
__device__ GFlag g_flag[NBLK];

__device__ __forceinline__ uint32_t smem_u32(const void* p) {
    uint32_t a;
    asm("{ .reg .u64 t; cvta.to.shared.u64 t, %1; cvt.u32.u64 %0, t; }" : "=r"(a) : "l"(p));
    return a;
}

// Hardware tanh (1 MUFU). Saturates cleanly; max rel err ~2^-11.
__device__ __forceinline__ float tanh_ap(float x) {
    float y;
    asm("tanh.approx.f32 %0, %1;" : "=f"(y) : "f"(x));
    return y;
}
__device__ __forceinline__ float sigmoid_ap(float x) {
    return fmaf(0.5f, tanh_ap(0.5f * x), 0.5f);
}

// m16n8k16 row.col bf16 -> fp32 accumulate (baseline PTX)
__device__ __forceinline__ void mma16816(float& c0, float& c1, float& c2, float& c3,
                                         uint32_t a0, uint32_t a1, uint32_t a2, uint32_t a3,
                                         uint32_t b0, uint32_t b1) {
    asm volatile(
        "mma.sync.aligned.m16n8k16.row.col.f32.bf16.bf16.f32 "
        "{%0,%1,%2,%3}, {%4,%5,%6,%7}, {%8,%9}, {%0,%1,%2,%3};"
        : "+f"(c0), "+f"(c1), "+f"(c2), "+f"(c3)
        : "r"(a0), "r"(a1), "r"(a2), "r"(a3), "r"(b0), "r"(b1));
}

// ldmatrix x4 (baseline PTX sm_75+)
#define LDSM4(r, addr) \
    asm volatile("ldmatrix.sync.aligned.m8n8.x4.shared.b16 {%0,%1,%2,%3}, [%4];" \
        : "=r"((r)[0]), "=r"((r)[1]), "=r"((r)[2]), "=r"((r)[3]) : "r"(addr))

// One K-half (8 k-chunks) of the 3-pass MMA. kbase = 0 or 256 bytes.
__device__ __forceinline__ void mma_half(float acc[2][4][4],
                                         uint32_t ahi0, uint32_t alo0,
                                         uint32_t bhi0, uint32_t blo0, int kbase)
{
#pragma unroll 2
    for (int kc = 0; kc < 8; kc++) {
        const int kb = kbase + kc * 32;   // 16 bf16 = 32 bytes
        uint32_t ah0[4], ah1[4], al0[4], al1[4];
        uint32_t bh0[4], bh1[4], bl0[4], bl1[4];
        LDSM4(ah0, ahi0 + kb);
        LDSM4(ah1, ahi0 + 16 * KPB + kb);
        LDSM4(al0, alo0 + kb);
        LDSM4(al1, alo0 + 16 * KPB + kb);
        LDSM4(bh0, bhi0 + kb);
        LDSM4(bh1, bhi0 + 16 * KPB + kb);
        LDSM4(bl0, blo0 + kb);
        LDSM4(bl1, blo0 + 16 * KPB + kb);
        uint32_t* ahp[2] = {ah0, ah1};
        uint32_t* alp[2] = {al0, al1};
        uint32_t* bhj[4] = {bh0, bh0 + 2, bh1, bh1 + 2};
        uint32_t* blj[4] = {bl0, bl0 + 2, bl1, bl1 + 2};
#pragma unroll
        for (int j = 0; j < 4; j++) {
#pragma unroll
            for (int ms = 0; ms < 2; ms++) {
                mma16816(acc[ms][j][0], acc[ms][j][1], acc[ms][j][2], acc[ms][j][3],
                         ahp[ms][0], ahp[ms][1], ahp[ms][2], ahp[ms][3],
                         bhj[j][0], bhj[j][1]);
                mma16816(acc[ms][j][0], acc[ms][j][1], acc[ms][j][2], acc[ms][j][3],
                         alp[ms][0], alp[ms][1], alp[ms][2], alp[ms][3],
                         bhj[j][0], bhj[j][1]);
                mma16816(acc[ms][j][0], acc[ms][j][1], acc[ms][j][2], acc[ms][j][3],
                         ahp[ms][0], ahp[ms][1], ahp[ms][2], ahp[ms][3],
                         blj[j][0], blj[j][1]);
            }
        }
    }
}

extern "C" __global__ void __launch_bounds__(NTHR, 1)
lstm_hmma_kernel(const int*   __restrict__ inputs,   // [NB, SEQT]
                 const float* __restrict__ Wx,       // [NCHARS, ZC]
                 const float* __restrict__ Wh,       // [UNITS, ZC]
                 const float* __restrict__ bias,     // [ZC]
                 const float* __restrict__ Wd,       // [UNITS, NCHARS]
                 const float* __restrict__ bd,       // [NCHARS]
                 float*       __restrict__ out)      // [NB, NCHARS]
{
    extern __shared__ char smem[];
    float* z_s = (float*)(smem + OFF_Z);
    const uint32_t sb = smem_u32(smem);
    __shared__ unsigned int fbase_s;

    const int tid  = threadIdx.x;
    const int wid  = tid >> 5;
    const int lane = tid & 31;
    const int bt   = blockIdx.x >> 3;   // 0..15 (barrier group)
    const int ht   = blockIdx.x & 7;    // 0..7
    const int b0   = bt * BM;

    // Flag epoch base: own flag's persisted value (uniform across blocks =
    // launches*SEQT; zero on first launch). Makes the monotonic flags
    // replay-safe without any reset.
    if (tid == 0) fbase_s = g_flag[blockIdx.x].v;

    // ---- One-time: Wh slice -> bf16 hi/lo, INTERLEAVED cols: n = 4*unit + gate ----
    // local col n -> global col: gate(n&3)*256 + ht*32 + unit(n>>2)
    for (int idx = tid; idx < BC * KDIM; idx += NTHR) {
        int n = idx >> 8;          // 0..127
        int k = idx & 255;         // 0..255
        int gcol = ((n & 3) << 8) + ht * HN + (n >> 2);
        float w = Wh[k * ZC + gcol];
        __nv_bfloat16 hi = __float2bfloat16(w);
        __nv_bfloat16 lo = __float2bfloat16(w - __bfloat162float(hi));
        *(__nv_bfloat16*)(smem + OFF_WHI + n * KPB + k * 2) = hi;
        *(__nv_bfloat16*)(smem + OFF_WLO + n * KPB + k * 2) = lo;
    }

    // Bias -> registers (coalesced: u = lane)
    const int u = lane;
    float breg[4];
#pragma unroll
    for (int gt = 0; gt < 4; gt++)
        breg[gt] = __ldg(&bias[gt * 256 + ht * HN + u]);

    // zero z region (t=0 gate phase reads zeros)
    for (int idx = tid; idx < BM * ZP; idx += NTHR) z_s[idx] = 0.0f;

    float creg[8];
#pragma unroll
    for (int j = 0; j < 8; j++) creg[j] = 0.0f;

    // MMA warp mapping: warp tile m32 x n32; Wm=2 (wm=wid&1), Wn=4 (wn=wid>>1)
    const int g  = lane >> 2;      // 0..7
    const int tg = lane & 3;       // 0..3
    const int wm = wid & 1;
    const int wn = wid >> 1;

    // ldmatrix per-lane row addresses (x4 matrix order matches mma frag order)
    const int l7 = lane & 7;
    const int qq = lane >> 3;      // quad 0..3
    const uint32_t ahi0 = sb + OFF_AHI + (uint32_t)((32 * wm + l7 + 8 * (qq & 1)) * KPB + 16 * (qq >> 1));
    const uint32_t alo0 = sb + OFF_ALO + (uint32_t)((32 * wm + l7 + 8 * (qq & 1)) * KPB + 16 * (qq >> 1));
    const uint32_t bhi0 = sb + OFF_WHI + (uint32_t)((32 * wn + 8 * (qq >> 1) + l7) * KPB + 16 * (qq & 1));
    const uint32_t blo0 = sb + OFF_WLO + (uint32_t)((32 * wn + 8 * (qq >> 1) + l7) * KPB + 16 * (qq & 1));

    __syncthreads();
    const unsigned int fbase = fbase_s;

    // ---- Prefetch chars + Wx gather for t = 0 ----
    int   ch[8];
    float xv0[8], xv1[8], xv2[8], xv3[8];
#pragma unroll
    for (int j = 0; j < 8; j++)
        ch[j] = __ldg(&inputs[(b0 + wid + 8 * j) * SEQT + 0]);
#pragma unroll
    for (int j = 0; j < 8; j++) {
        const float* wxr = Wx + ch[j] * ZC + ht * HN + u;
        xv0[j] = __ldg(wxr);
        xv1[j] = __ldg(wxr + 256);
        xv2[j] = __ldg(wxr + 512);
        xv3[j] = __ldg(wxr + 768);
    }

    for (int t = 0; t < SEQT; t++) {
        const int cur = t & 1;
        const int nxt = cur ^ 1;

        if (t > 0) {
            // ---- Stage A lower K half: k in [0,128) ----
            uint4 pp[8];
#pragma unroll
            for (int i = 0; i < 8; i++) {
                int gidx = tid + i * NTHR;      // over BM*32 groups
                int r  = gidx >> 5;
                int kq = gidx & 31;             // k0 = 4*kq
                uint4 p = *(const uint4*)&g_hx[cur][(b0 + r) * UNITS_ + 4 * kq];
                uint32_t hi01 = __byte_perm(p.x, p.y, 0x5410);
                uint32_t hi23 = __byte_perm(p.z, p.w, 0x5410);
                uint32_t lo01 = __byte_perm(p.x, p.y, 0x7632);
                uint32_t lo23 = __byte_perm(p.z, p.w, 0x7632);
                uint32_t byte = (uint32_t)(r * KPB + 8 * kq);
                *(uint2*)(smem + OFF_AHI + byte) = make_uint2(hi01, hi23);
                *(uint2*)(smem + OFF_ALO + byte) = make_uint2(lo01, lo23);
            }
            // ---- Issue upper-half LDGs (latency hidden under lower-half MMA) ----
#pragma unroll
            for (int i = 0; i < 8; i++) {
                int gidx = tid + i * NTHR;
                int r  = gidx >> 5;
                int kq = 32 + (gidx & 31);
                pp[i] = *(const uint4*)&g_hx[cur][(b0 + r) * UNITS_ + 4 * kq];
            }

            float acc[2][4][4];
#pragma unroll
            for (int ms = 0; ms < 2; ms++)
#pragma unroll
                for (int j = 0; j < 4; j++) {
                    acc[ms][j][0] = 0.f; acc[ms][j][1] = 0.f;
                    acc[ms][j][2] = 0.f; acc[ms][j][3] = 0.f;
                }

            __syncthreads();   // lower-half staging visible

            // ---- MMA on lower K half (upper-half LDGs still in flight) ----
            mma_half(acc, ahi0, alo0, bhi0, blo0, 0);

            // ---- Store upper half (disjoint bytes from lower-half reads) ----
#pragma unroll
            for (int i = 0; i < 8; i++) {
                int gidx = tid + i * NTHR;
                int r  = gidx >> 5;
                int kq = 32 + (gidx & 31);
                uint4 p = pp[i];
                uint32_t hi01 = __byte_perm(p.x, p.y, 0x5410);
                uint32_t hi23 = __byte_perm(p.z, p.w, 0x5410);
                uint32_t lo01 = __byte_perm(p.x, p.y, 0x7632);
                uint32_t lo23 = __byte_perm(p.z, p.w, 0x7632);
                uint32_t byte = (uint32_t)(r * KPB + 8 * kq);
                *(uint2*)(smem + OFF_AHI + byte) = make_uint2(hi01, hi23);
                *(uint2*)(smem + OFF_ALO + byte) = make_uint2(lo01, lo23);
            }
            __syncthreads();   // upper-half staging visible

            // ---- MMA on upper K half ----
            mma_half(acc, ahi0, alo0, bhi0, blo0, 256);

            __syncthreads();   // all A reads done before z overlays A_hi

            // ---- Store z tile (m32n32 accumulator layout -> [row][col]) ----
#pragma unroll
            for (int ms = 0; ms < 2; ms++)
#pragma unroll
                for (int j = 0; j < 4; j++) {
                    int row0 = 32 * wm + 16 * ms + g;
                    int col  = 32 * wn + 8 * j + 2 * tg;
                    *(float2*)(z_s + row0 * ZP + col)       = make_float2(acc[ms][j][0], acc[ms][j][1]);
                    *(float2*)(z_s + (row0 + 8) * ZP + col) = make_float2(acc[ms][j][2], acc[ms][j][3]);
                }
            __syncthreads();
        }

        // ---- Gate phase: coalesced (b = wid + 8j); z cols interleaved 4u+gate ----
#pragma unroll
        for (int j = 0; j < 8; j++) {
            int b = wid + 8 * j;
            float4 q = *(const float4*)(z_s + b * ZP + 4 * u);
            float zi = q.x + xv0[j] + breg[0];
            float zf = q.y + xv1[j] + breg[1];
            float zg = q.z + xv2[j] + breg[2];
            float zo = q.w + xv3[j] + breg[3];
            float ig = sigmoid_ap(zi);
            float fg = sigmoid_ap(zf);
            float og = sigmoid_ap(zo);
            float gg = tanh_ap(zg);
            float c  = fmaf(fg, creg[j], ig * gg);
            creg[j] = c;
            float h  = og * tanh_ap(c);
            __nv_bfloat16 hh = __float2bfloat16(h);
            __nv_bfloat16 hl = __float2bfloat16(h - __bfloat162float(hh));
            unsigned int word = (unsigned int)__bfloat16_as_ushort(hh) |
                                ((unsigned int)__bfloat16_as_ushort(hl) << 16);
            g_hx[nxt][(b0 + b) * UNITS_ + ht * HN + u] = word;
        }

        // ---- Split barrier: arrive, prefetch t+1 gather, then wait ----
        __syncthreads();                 // all warps' h stores issued
        if (tid == 0) {
            __threadfence();             // order h stores before flag
            asm volatile("st.global.release.gpu.u32 [%0], %1;"
                         :: "l"(&g_flag[blockIdx.x].v), "r"(fbase + t + 1) : "memory");
        }

        if (t + 1 < SEQT) {              // gather for t+1 drains during the wait
#pragma unroll
            for (int j = 0; j < 8; j++)
                ch[j] = __ldg(&inputs[(b0 + wid + 8 * j) * SEQT + (t + 1)]);
#pragma unroll
            for (int j = 0; j < 8; j++) {
                const float* wxr = Wx + ch[j] * ZC + ht * HN + u;
                xv0[j] = __ldg(wxr);
                xv1[j] = __ldg(wxr + 256);
                xv2[j] = __ldg(wxr + 512);
                xv3[j] = __ldg(wxr + 768);
            }
        }

        if (tid < GRPSZ) {               // warp-0 lanes poll the 8 group flags
            const unsigned int tgt = fbase + t + 1;
            unsigned int v;
            do {
                asm volatile("ld.global.acquire.gpu.u32 %0, [%1];"
                             : "=r"(v) : "l"(&g_flag[bt * GRPSZ + tid].v) : "memory");
            } while (v < tgt);
        }
        __syncthreads();
    }

    // ---- Final stage: logits = h_final @ Wd + bd ; softmax ----
    const int rowbase = blockIdx.x * 8;
    float* wd_s   = (float*)smem;               // 128KB (WHI+WLO region)
    float* hrow_s = (float*)(smem + OFF_ALO);   // 8x256 fp32
    float* lg     = (float*)(smem + OFF_ALO + 8 * 256 * 4); // 8x128 logits

    for (int idx = tid; idx < UNITS_ * NCHARS; idx += NTHR)
        wd_s[idx] = Wd[idx];
    for (int idx = tid; idx < 8 * UNITS_; idx += NTHR) {
        int r  = idx >> 8;
        int uu = idx & 255;
        unsigned int word = g_hx[0][(rowbase + r) * UNITS_ + uu];
        float h = __bfloat162float(__ushort_as_bfloat16((unsigned short)(word & 0xFFFF))) +
                  __bfloat162float(__ushort_as_bfloat16((unsigned short)(word >> 16)));
        hrow_s[idx] = h;
    }
    __syncthreads();

    {
        int n  = tid & 127;
        int rr = tid >> 7;
#pragma unroll
        for (int q = 0; q < 4; q++) {
            int row = q * 2 + rr;
            float a = bd[n];
#pragma unroll 8
            for (int uu = 0; uu < UNITS_; uu++)
                a = fmaf(hrow_s[row * UNITS_ + uu], wd_s[uu * NCHARS + n], a);
            lg[row * NCHARS + n] = a;
        }
    }
    __syncthreads();

    {   // softmax: one warp per row (accurate __expf path)
        int w = tid >> 5;
        float v[4];
        float mx = -3.402823466e38f;
#pragma unroll
        for (int q = 0; q < 4; q++) {
            v[q] = lg[w * NCHARS + lane + 32 * q];
            mx = fmaxf(mx, v[q]);
        }
#pragma unroll
        for (int s = 16; s > 0; s >>= 1) mx = fmaxf(mx, __shfl_xor_sync(0xFFFFFFFFu, mx, s));
        float sum = 0.f;
#pragma unroll
        for (int q = 0; q < 4; q++) { v[q] = __expf(v[q] - mx); sum += v[q]; }
#pragma unroll
        for (int s = 16; s > 0; s >>= 1) sum += __shfl_xor_sync(0xFFFFFFFFu, sum, s);
        float inv = 1.0f / sum;
        int bg = rowbase + w;
#pragma unroll
        for (int q = 0; q < 4; q++)
            out[bg * NCHARS + lane + 32 * q] = v[q] * inv;
    }
}

extern "C" void kernel_launch(void* const* d_in, const int* in_sizes, int n_in,
                              void* d_out, int out_size) {
    const int*   inputs = (const int*)  d_in[0];
    const float* Wx     = (const float*)d_in[1];
    const float* Wh     = (const float*)d_in[2];
    const float* b      = (const float*)d_in[3];
    const float* Wd     = (const float*)d_in[4];
    const float* bd     = (const float*)d_in[5];
    float* out = (float*)d_out;

    cudaFuncSetAttribute(lstm_hmma_kernel,
                         cudaFuncAttributeMaxDynamicSharedMemorySize, SMEM_TOTAL);

    lstm_hmma_kernel<<<NBLK, NTHR, SMEM_TOTAL>>>(inputs, Wx, Wh, b, Wd, bd, out);
}